// round 8
// baseline (speedup 1.0000x reference)
#include <cuda_runtime.h>
#include <cuda_bf16.h>

#define NN 100000
#define EE 1600000
#define BB 256
#define NCH 98          // ceil(NN / 1024)

// ---- scratch (device globals; no allocation allowed) ----
__device__ __align__(128) float g_h[(size_t)NN * 128];            // fp32 hs
__device__ __align__(128) __nv_bfloat16 g_hb[(size_t)NN * 128];   // bf16 hs (gather path)
__device__ __align__(128) float g_act[(size_t)NN * 128];          // activations
__device__ __align__(128) float g_dis[NN];                        // rsqrt(deg+1)
__device__ int   g_deg[NN];
__device__ int   g_off[NN];
__device__ int   g_cur[NN];
__device__ int   g_scan[NN];
__device__ int   g_bsum[NCH + 1];
__device__ int   g_boff[NCH + 1];
__device__ int   g_esrc[EE];
__device__ __align__(128) float g_sums[BB * 128];
__device__ float g_cnt[BB];
__device__ int   g_is64;

__device__ __forceinline__ void red_add_v4(float* addr, float4 v) {
    unsigned long long ga = (unsigned long long)__cvta_generic_to_global(addr);
    asm volatile("red.global.add.v4.f32 [%0], {%1,%2,%3,%4};"
                 :: "l"(ga), "f"(v.x), "f"(v.y), "f"(v.z), "f"(v.w) : "memory");
}

__device__ __forceinline__ int load_idx(const void* p, long long i) {
    return g_is64 ? (int)((const long long*)p)[i] : ((const int*)p)[i];
}

// ---- init: zero counters + dtype detection ----
__global__ void k_init(const int* __restrict__ raw) {
    int i = blockIdx.x * blockDim.x + threadIdx.x;
    if (i < NN) g_deg[i] = 0;
    if (i < BB * 128) g_sums[i] = 0.f;
    if (i < BB) g_cnt[i] = 0.f;
    if (i == 0) {
        int nz = 0;
        for (int j = 1; j < 256; j += 2) nz += (raw[j] != 0);
        g_is64 = (nz == 0) ? 1 : 0;
    }
}

// ---- histogram of in-degrees ----
__global__ void k_hist(const void* __restrict__ ei) {
    int e = blockIdx.x * blockDim.x + threadIdx.x;
    if (e >= EE) return;
    int d = load_idx(ei, (long long)EE + e);
    if ((unsigned)d >= NN) d = 0;
    atomicAdd(&g_deg[d], 1);
}

// ---- scan stage 1: per-1024-chunk inclusive scan (Kogge-Stone) ----
__global__ void k_scan1() {
    __shared__ int s[1024];
    int t = threadIdx.x;
    int i = blockIdx.x * 1024 + t;
    int v = (i < NN) ? g_deg[i] : 0;
    s[t] = v;
    __syncthreads();
    #pragma unroll
    for (int d = 1; d < 1024; d <<= 1) {
        int add = (t >= d) ? s[t - d] : 0;
        __syncthreads();
        s[t] += add;
        __syncthreads();
    }
    if (i < NN) g_scan[i] = s[t];
    if (t == 1023) g_bsum[blockIdx.x] = s[1023];
}

// ---- scan stage 2: parallel exclusive scan of chunk totals ----
__global__ void k_scan2() {
    __shared__ int s[128];
    int t = threadIdx.x;
    int v = (t < NCH) ? g_bsum[t] : 0;
    s[t] = v;
    __syncthreads();
    #pragma unroll
    for (int d = 1; d < 128; d <<= 1) {
        int add = (t >= d) ? s[t - d] : 0;
        __syncthreads();
        s[t] += add;
        __syncthreads();
    }
    if (t < NCH) g_boff[t] = s[t] - v;   // exclusive
}

// ---- scan stage 3: finalize offsets + dis + seed sort cursor ----
__global__ void k_scan3() {
    int i = blockIdx.x * blockDim.x + threadIdx.x;
    if (i >= NN) return;
    int dg = g_deg[i];
    int off = g_boff[i >> 10] + g_scan[i] - dg;
    g_off[i] = off;
    g_cur[i] = off;
    g_dis[i] = rsqrtf((float)dg + 1.f);
}

// ---- counting-sort edges by dst ----
__global__ void k_sort(const void* __restrict__ ei) {
    int e = blockIdx.x * blockDim.x + threadIdx.x;
    if (e >= EE) return;
    int s = load_idx(ei, e);
    int d = load_idx(ei, (long long)EE + e);
    if ((unsigned)s >= NN) s = 0;
    if ((unsigned)d >= NN) d = 0;
    int p = atomicAdd(&g_cur[d], 1);
    g_esrc[p] = s;
}

// ---- GEMM: hs = (A @ W) * dis; writes fp32 g_h + bf16 g_hb ----
template <int FIN, int FOUT, int NPB, bool FROM_ACT>
__global__ void k_gemm(const float* __restrict__ Aext, const float* __restrict__ W) {
    const float* __restrict__ A = FROM_ACT ? (const float*)g_act : Aext;
    constexpr int FG  = FOUT / 4;
    constexpr int RS  = 256 / FG;
    constexpr int RPT = NPB / RS;
    __shared__ float sW[FIN * FOUT];
    __shared__ float sX[NPB * FIN];
    const int tid = threadIdx.x;
    if constexpr ((FIN * FOUT) % 1024 == 0) {
        for (int i = tid; i < FIN * FOUT / 4; i += 256)
            reinterpret_cast<float4*>(sW)[i] = reinterpret_cast<const float4*>(W)[i];
    } else {
        for (int i = tid; i < FIN * FOUT; i += 256) sW[i] = W[i];
    }
    const int n0 = blockIdx.x * NPB;
    for (int i = tid; i < NPB * FIN; i += 256) {
        int nn = i / FIN, k = i % FIN;
        int n = n0 + nn;
        sX[i] = (n < NN) ? A[(size_t)n * FIN + k] : 0.f;
    }
    __syncthreads();
    const int fg = tid % FG;
    const int rs = tid / FG;
    float4 acc[RPT];
    #pragma unroll
    for (int r = 0; r < RPT; r++) acc[r] = make_float4(0.f, 0.f, 0.f, 0.f);
    #pragma unroll
    for (int k = 0; k < FIN; k++) {
        float4 w = *reinterpret_cast<const float4*>(&sW[k * FOUT + fg * 4]);
        #pragma unroll
        for (int r = 0; r < RPT; r++) {
            float xv = sX[(rs + r * RS) * FIN + k];
            acc[r].x = fmaf(xv, w.x, acc[r].x);
            acc[r].y = fmaf(xv, w.y, acc[r].y);
            acc[r].z = fmaf(xv, w.z, acc[r].z);
            acc[r].w = fmaf(xv, w.w, acc[r].w);
        }
    }
    #pragma unroll
    for (int r = 0; r < RPT; r++) {
        int n = n0 + rs + r * RS;
        if (n >= NN) continue;
        float ds = g_dis[n];
        float4 o = make_float4(acc[r].x * ds, acc[r].y * ds, acc[r].z * ds, acc[r].w * ds);
        size_t off = (size_t)n * FOUT + fg * 4;
        *reinterpret_cast<float4*>(g_h + off) = o;
        __nv_bfloat162 p0 = __floats2bfloat162_rn(o.x, o.y);
        __nv_bfloat162 p1 = __floats2bfloat162_rn(o.z, o.w);
        uint2 pk;
        pk.x = *reinterpret_cast<unsigned*>(&p0);
        pk.y = *reinterpret_cast<unsigned*>(&p1);
        *reinterpret_cast<uint2*>(g_hb + off) = pk;
    }
}

// ---- fused aggregation + BN + ReLU, 64-wide: ONE WARP PER NODE ----
// Lane-parallel index prefetch (1 coalesced LDG per 32 edges) + shfl broadcast;
// per edge one warp-wide 128B bf16 row load, fully independent -> high MLP.
__global__ void k_agg64(const float* __restrict__ b, const float* __restrict__ g,
                        const float* __restrict__ be, const float* __restrict__ m,
                        const float* __restrict__ v) {
    int n = (blockIdx.x * blockDim.x + threadIdx.x) >> 5;
    if (n >= NN) return;
    int lane = threadIdx.x & 31;
    int f = lane * 2;
    float2 acc = *reinterpret_cast<const float2*>(g_h + (size_t)n * 64 + f);  // self
    const unsigned* hb = reinterpret_cast<const unsigned*>(g_hb);  // 32 u32 per row
    int p = g_off[n];
    int rem = g_deg[n];
    while (rem > 0) {
        int cnt = rem < 32 ? rem : 32;
        int idx = (lane < cnt) ? __ldg(&g_esrc[p + lane]) : 0;
        #pragma unroll 4
        for (int e = 0; e < cnt; e++) {
            int s = __shfl_sync(0xffffffffu, idx, e);
            unsigned pk = __ldg(&hb[(size_t)s * 32 + lane]);
            float2 f2 = __bfloat1622float2(*reinterpret_cast<__nv_bfloat162*>(&pk));
            acc.x += f2.x;
            acc.y += f2.y;
        }
        p += cnt;
        rem -= cnt;
    }
    float dis = g_dis[n];
    float sc0 = __ldg(&g[f])     * rsqrtf(__ldg(&v[f])     + 1e-5f);
    float sc1 = __ldg(&g[f + 1]) * rsqrtf(__ldg(&v[f + 1]) + 1e-5f);
    float2 o;
    o.x = fmaxf((dis * acc.x + __ldg(&b[f])     - __ldg(&m[f]))     * sc0 + __ldg(&be[f]),     0.f);
    o.y = fmaxf((dis * acc.y + __ldg(&b[f + 1]) - __ldg(&m[f + 1])) * sc1 + __ldg(&be[f + 1]), 0.f);
    *reinterpret_cast<float2*>(g_act + (size_t)n * 64 + f) = o;
}

// ---- fused aggregation + relu + mean-pool, 128-wide: ONE WARP PER NODE ----
__global__ void k_agg128(const float* __restrict__ b3, const void* __restrict__ batch) {
    int n = (blockIdx.x * blockDim.x + threadIdx.x) >> 5;
    if (n >= NN) return;
    int lane = threadIdx.x & 31;
    int f = lane * 4;
    float4 acc = *reinterpret_cast<const float4*>(g_h + (size_t)n * 128 + f);  // self
    const uint2* hb = reinterpret_cast<const uint2*>(g_hb);  // 32 uint2 per row
    int p = g_off[n];
    int rem = g_deg[n];
    while (rem > 0) {
        int cnt = rem < 32 ? rem : 32;
        int idx = (lane < cnt) ? __ldg(&g_esrc[p + lane]) : 0;
        #pragma unroll 4
        for (int e = 0; e < cnt; e++) {
            int s = __shfl_sync(0xffffffffu, idx, e);
            uint2 pk = __ldg(&hb[(size_t)s * 32 + lane]);
            float2 f0 = __bfloat1622float2(*reinterpret_cast<__nv_bfloat162*>(&pk.x));
            float2 f1 = __bfloat1622float2(*reinterpret_cast<__nv_bfloat162*>(&pk.y));
            acc.x += f0.x; acc.y += f0.y; acc.z += f1.x; acc.w += f1.y;
        }
        p += cnt;
        rem -= cnt;
    }
    float dis = g_dis[n];
    float4 o;
    o.x = fmaxf(dis * acc.x + __ldg(&b3[f + 0]), 0.f);
    o.y = fmaxf(dis * acc.y + __ldg(&b3[f + 1]), 0.f);
    o.z = fmaxf(dis * acc.z + __ldg(&b3[f + 2]), 0.f);
    o.w = fmaxf(dis * acc.w + __ldg(&b3[f + 3]), 0.f);
    int bg = load_idx(batch, n);
    if ((unsigned)bg >= BB) bg = 0;
    red_add_v4(g_sums + bg * 128 + f, o);
    if (lane == 0) atomicAdd(&g_cnt[bg], 1.f);
}

// ---- finalize: out[b,f] = sums / max(cnt, 1) ----
__global__ void k_final(float* __restrict__ out) {
    int i = blockIdx.x * blockDim.x + threadIdx.x;
    if (i >= BB * 128) return;
    out[i] = g_sums[i] / fmaxf(g_cnt[i >> 7], 1.f);
}

extern "C" void kernel_launch(void* const* d_in, const int* in_sizes, int n_in,
                              void* d_out, int out_size) {
    const float* x   = (const float*)d_in[0];
    const void*  ei  = d_in[1];
    const void*  bat = d_in[2];
    const float* W1 = (const float*)d_in[3];
    const float* b1 = (const float*)d_in[4];
    const float* W2 = (const float*)d_in[5];
    const float* b2 = (const float*)d_in[6];
    const float* W3 = (const float*)d_in[7];
    const float* b3 = (const float*)d_in[8];
    const float* g1 = (const float*)d_in[9];
    const float* be1 = (const float*)d_in[10];
    const float* m1 = (const float*)d_in[11];
    const float* v1 = (const float*)d_in[12];
    const float* g2 = (const float*)d_in[13];
    const float* be2 = (const float*)d_in[14];
    const float* m2 = (const float*)d_in[15];
    const float* v2 = (const float*)d_in[16];

    const int TB = 256;

    // CSR construction
    k_init<<<(NN + TB - 1) / TB, TB>>>((const int*)ei);
    k_hist<<<(EE + TB - 1) / TB, TB>>>(ei);
    k_scan1<<<NCH, 1024>>>();
    k_scan2<<<1, 128>>>();
    k_scan3<<<(NN + TB - 1) / TB, TB>>>();
    k_sort<<<(EE + TB - 1) / TB, TB>>>(ei);

    // ---- layer 1: 22 -> 64 ----
    k_gemm<22, 64, 32, false><<<(NN + 31) / 32, TB>>>(x, W1);
    k_agg64<<<(NN * 32 + TB - 1) / TB, TB>>>(b1, g1, be1, m1, v1);

    // ---- layer 2: 64 -> 64 ----
    k_gemm<64, 64, 32, true><<<(NN + 31) / 32, TB>>>(nullptr, W2);
    k_agg64<<<(NN * 32 + TB - 1) / TB, TB>>>(b2, g2, be2, m2, v2);

    // ---- layer 3: 64 -> 128, fused pooling ----
    k_gemm<64, 128, 16, true><<<(NN + 15) / 16, TB>>>(nullptr, W3);
    k_agg128<<<(NN * 32 + TB - 1) / TB, TB>>>(b3, bat);
    k_final<<<(BB * 128 + TB - 1) / TB, TB>>>((float*)d_out);
}

// round 9
// speedup vs baseline: 1.1248x; 1.1248x over previous
#include <cuda_runtime.h>
#include <cuda_bf16.h>

#define NN 100000
#define EE 1600000
#define BB 256
#define NCH 98          // ceil(NN / 1024)
#define GBK 3125        // gemm blocks, layer 1 (32 rows each)
#define EBK 6250        // edge blocks (256 edges each)

// ---- scratch (device globals; zero at load; recycled via end-of-call cleanup) ----
__device__ __align__(128) float g_h[(size_t)NN * 128];            // fp32 h / hs
__device__ __align__(128) __nv_bfloat16 g_hb[(size_t)NN * 128];   // bf16 copy (gather path)
__device__ __align__(128) float g_act[(size_t)NN * 128];          // activations
__device__ __align__(128) float g_dis[NN];                        // rsqrt(deg+1)
__device__ int   g_deg[NN];     // in-degree   (zeroed by k_final for next call)
__device__ int   g_cur[NN];     // sort cursor (zeroed by k_final)
__device__ int   g_scan[NN];    // chunk-local inclusive scan
__device__ int   g_bsum[NCH];
__device__ int   g_boff[NCH];
__device__ int   g_esrc[EE];
__device__ int   g_tick;        // scan12 ticket (zeroed by k_final)
__device__ __align__(128) float g_sums[BB * 128];  // zeroed by launch 0
__device__ float g_cnt[BB];                        // zeroed by launch 0
__device__ int   g_is64;

__device__ __forceinline__ void red_add_v4(float* addr, float4 v) {
    unsigned long long ga = (unsigned long long)__cvta_generic_to_global(addr);
    asm volatile("red.global.add.v4.f32 [%0], {%1,%2,%3,%4};"
                 :: "l"(ga), "f"(v.x), "f"(v.y), "f"(v.z), "f"(v.w) : "memory");
}

// per-warp dtype detection: int64 storage of small ints -> odd 32-bit words all zero
__device__ __forceinline__ int detect64(const int* raw) {
    int lane = threadIdx.x & 31;
    int w = (lane < 16) ? raw[2 * lane + 1] : 0;
    return __ballot_sync(0xffffffffu, w != 0) == 0u;
}

__device__ __forceinline__ int load_idx64(const void* p, long long i, int is64) {
    return is64 ? (int)((const long long*)p)[i] : ((const int*)p)[i];
}

// accumulate 8 bf16 (one uint4) into 8 fp32 accumulators, scaled by s
__device__ __forceinline__ void acc8s(float* acc, uint4 pk, float s) {
    const __nv_bfloat162* b2 = reinterpret_cast<const __nv_bfloat162*>(&pk);
    #pragma unroll
    for (int j = 0; j < 4; j++) {
        float2 f2 = __bfloat1622float2(b2[j]);
        acc[j * 2 + 0] = fmaf(f2.x, s, acc[j * 2 + 0]);
        acc[j * 2 + 1] = fmaf(f2.y, s, acc[j * 2 + 1]);
    }
}

// ---- launch 0: layer-1 GEMM (unscaled) + edge histogram + pool zero + is64 ----
__global__ void k_l1(const float* __restrict__ x, const float* __restrict__ W,
                     const void* __restrict__ ei) {
    const int tid = threadIdx.x;
    if (blockIdx.x < GBK) {
        // ---- GEMM part: h = x @ W1 (22 -> 64), NPB=32 rows ----
        constexpr int FIN = 22, FOUT = 64, NPB = 32;
        constexpr int FG = FOUT / 4, RS = 256 / FG, RPT = NPB / RS;
        __shared__ float sW[FIN * FOUT];
        __shared__ float sX[NPB * FIN];
        for (int i = tid; i < FIN * FOUT; i += 256) sW[i] = W[i];
        const int n0 = blockIdx.x * NPB;
        for (int i = tid; i < NPB * FIN; i += 256) {
            int nn = i / FIN, k = i % FIN;
            int n = n0 + nn;
            sX[i] = (n < NN) ? x[(size_t)n * FIN + k] : 0.f;
        }
        __syncthreads();
        const int fg = tid % FG, rs = tid / FG;
        float4 acc[RPT];
        #pragma unroll
        for (int r = 0; r < RPT; r++) acc[r] = make_float4(0.f, 0.f, 0.f, 0.f);
        #pragma unroll
        for (int k = 0; k < FIN; k++) {
            float4 w = *reinterpret_cast<const float4*>(&sW[k * FOUT + fg * 4]);
            #pragma unroll
            for (int r = 0; r < RPT; r++) {
                float xv = sX[(rs + r * RS) * FIN + k];
                acc[r].x = fmaf(xv, w.x, acc[r].x);
                acc[r].y = fmaf(xv, w.y, acc[r].y);
                acc[r].z = fmaf(xv, w.z, acc[r].z);
                acc[r].w = fmaf(xv, w.w, acc[r].w);
            }
        }
        #pragma unroll
        for (int r = 0; r < RPT; r++) {
            int n = n0 + rs + r * RS;
            if (n >= NN) continue;
            size_t off = (size_t)n * FOUT + fg * 4;
            *reinterpret_cast<float4*>(g_h + off) = acc[r];
            __nv_bfloat162 p0 = __floats2bfloat162_rn(acc[r].x, acc[r].y);
            __nv_bfloat162 p1 = __floats2bfloat162_rn(acc[r].z, acc[r].w);
            uint2 pk;
            pk.x = *reinterpret_cast<unsigned*>(&p0);
            pk.y = *reinterpret_cast<unsigned*>(&p1);
            *reinterpret_cast<uint2*>(g_hb + off) = pk;
        }
    } else {
        // ---- edge part: histogram + pool zero + publish is64 ----
        int e = (blockIdx.x - GBK) * 256 + tid;
        int is64 = detect64((const int*)ei);
        if (e < BB * 128) g_sums[e] = 0.f;
        if (e < BB) g_cnt[e] = 0.f;
        if (e == 0) g_is64 = is64;
        if (e >= EE) return;
        int d = load_idx64(ei, (long long)EE + e, is64);
        if ((unsigned)d >= NN) d = 0;
        atomicAdd(&g_deg[d], 1);
    }
}

// ---- launch 1: chunk scans + dis, last block scans chunk totals ----
__global__ void k_scan12() {
    __shared__ int s[1024];
    __shared__ int s2[128];
    __shared__ int slast;
    int t = threadIdx.x;
    int i = blockIdx.x * 1024 + t;
    int v = (i < NN) ? g_deg[i] : 0;
    if (i < NN) g_dis[i] = rsqrtf((float)v + 1.f);
    s[t] = v;
    __syncthreads();
    #pragma unroll
    for (int d = 1; d < 1024; d <<= 1) {
        int add = (t >= d) ? s[t - d] : 0;
        __syncthreads();
        s[t] += add;
        __syncthreads();
    }
    if (i < NN) g_scan[i] = s[t];
    if (t == 1023) g_bsum[blockIdx.x] = s[1023];
    __threadfence();
    __syncthreads();
    if (t == 0) slast = (atomicAdd(&g_tick, 1) == NCH - 1) ? 1 : 0;
    __syncthreads();
    if (slast) {
        __threadfence();
        int v2 = (t < NCH) ? g_bsum[t] : 0;
        if (t < 128) s2[t] = v2;
        __syncthreads();
        #pragma unroll
        for (int d = 1; d < 128; d <<= 1) {
            int add = (t >= d && t < 128) ? s2[t - d] : 0;
            __syncthreads();
            if (t < 128) s2[t] += add;
            __syncthreads();
        }
        if (t < NCH) g_boff[t] = s2[t] - v2;   // exclusive
    }
}

// ---- launch 2: counting-sort edges by dst (off computed on the fly) ----
__global__ void k_sort(const void* __restrict__ ei) {
    int e = blockIdx.x * 256 + threadIdx.x;
    int is64 = detect64((const int*)ei);
    if (e >= EE) return;
    int sIdx = load_idx64(ei, e, is64);
    int d = load_idx64(ei, (long long)EE + e, is64);
    if ((unsigned)sIdx >= NN) sIdx = 0;
    if ((unsigned)d >= NN) d = 0;
    int off = g_boff[d >> 10] + g_scan[d] - g_deg[d];
    int p = off + atomicAdd(&g_cur[d], 1);
    g_esrc[p] = sIdx;
}

// ---- GEMM layers 2/3: hs = (act @ W) * dis ----
template <int FIN, int FOUT, int NPB>
__global__ void k_gemm(const float* __restrict__ W) {
    const float* __restrict__ A = (const float*)g_act;
    constexpr int FG = FOUT / 4, RS = 256 / FG, RPT = NPB / RS;
    __shared__ float sW[FIN * FOUT];
    __shared__ float sX[NPB * FIN];
    const int tid = threadIdx.x;
    for (int i = tid; i < FIN * FOUT / 4; i += 256)
        reinterpret_cast<float4*>(sW)[i] = reinterpret_cast<const float4*>(W)[i];
    const int n0 = blockIdx.x * NPB;
    for (int i = tid; i < NPB * FIN; i += 256) {
        int nn = i / FIN, k = i % FIN;
        int n = n0 + nn;
        sX[i] = (n < NN) ? A[(size_t)n * FIN + k] : 0.f;
    }
    __syncthreads();
    const int fg = tid % FG, rs = tid / FG;
    float4 acc[RPT];
    #pragma unroll
    for (int r = 0; r < RPT; r++) acc[r] = make_float4(0.f, 0.f, 0.f, 0.f);
    #pragma unroll
    for (int k = 0; k < FIN; k++) {
        float4 w = *reinterpret_cast<const float4*>(&sW[k * FOUT + fg * 4]);
        #pragma unroll
        for (int r = 0; r < RPT; r++) {
            float xv = sX[(rs + r * RS) * FIN + k];
            acc[r].x = fmaf(xv, w.x, acc[r].x);
            acc[r].y = fmaf(xv, w.y, acc[r].y);
            acc[r].z = fmaf(xv, w.z, acc[r].z);
            acc[r].w = fmaf(xv, w.w, acc[r].w);
        }
    }
    #pragma unroll
    for (int r = 0; r < RPT; r++) {
        int n = n0 + rs + r * RS;
        if (n >= NN) continue;
        float ds = g_dis[n];
        float4 o = make_float4(acc[r].x * ds, acc[r].y * ds, acc[r].z * ds, acc[r].w * ds);
        size_t off = (size_t)n * FOUT + fg * 4;
        *reinterpret_cast<float4*>(g_h + off) = o;
        __nv_bfloat162 p0 = __floats2bfloat162_rn(o.x, o.y);
        __nv_bfloat162 p1 = __floats2bfloat162_rn(o.z, o.w);
        uint2 pk;
        pk.x = *reinterpret_cast<unsigned*>(&p0);
        pk.y = *reinterpret_cast<unsigned*>(&p1);
        *reinterpret_cast<uint2*>(g_hb + off) = pk;
    }
}

// ---- fused aggregation + BN + ReLU, 64-wide: 8 threads/node, 4-way unroll ----
// L1: h is unscaled -> apply dis[s] per edge (fma) and dis[n] on self.
template <bool L1>
__global__ void k_agg64(const float* __restrict__ b, const float* __restrict__ g,
                        const float* __restrict__ be, const float* __restrict__ m,
                        const float* __restrict__ v) {
    int t = blockIdx.x * blockDim.x + threadIdx.x;
    int n = t >> 3;
    if (n >= NN) return;
    int c = t & 7;
    int f = c * 8;
    int deg = g_deg[n];
    int off = g_boff[n >> 10] + g_scan[n] - deg;
    float dis = g_dis[n];
    float acc[8];
    {
        float4 a0 = *reinterpret_cast<const float4*>(g_h + (size_t)n * 64 + f);
        float4 a1 = *reinterpret_cast<const float4*>(g_h + (size_t)n * 64 + f + 4);
        float sc = L1 ? dis : 1.f;
        acc[0] = a0.x * sc; acc[1] = a0.y * sc; acc[2] = a0.z * sc; acc[3] = a0.w * sc;
        acc[4] = a1.x * sc; acc[5] = a1.y * sc; acc[6] = a1.z * sc; acc[7] = a1.w * sc;
    }
    const uint4* hb = reinterpret_cast<const uint4*>(g_hb);  // 8 uint4 per 64-row
    int p = off, end = off + deg;
    for (; p + 3 < end; p += 4) {
        int s0 = __ldg(&g_esrc[p]);
        int s1 = __ldg(&g_esrc[p + 1]);
        int s2 = __ldg(&g_esrc[p + 2]);
        int s3 = __ldg(&g_esrc[p + 3]);
        float d0 = L1 ? __ldg(&g_dis[s0]) : 1.f;
        float d1 = L1 ? __ldg(&g_dis[s1]) : 1.f;
        float d2 = L1 ? __ldg(&g_dis[s2]) : 1.f;
        float d3 = L1 ? __ldg(&g_dis[s3]) : 1.f;
        uint4 v0 = __ldg(&hb[(size_t)s0 * 8 + c]);
        uint4 v1 = __ldg(&hb[(size_t)s1 * 8 + c]);
        uint4 v2 = __ldg(&hb[(size_t)s2 * 8 + c]);
        uint4 v3 = __ldg(&hb[(size_t)s3 * 8 + c]);
        acc8s(acc, v0, d0);
        acc8s(acc, v1, d1);
        acc8s(acc, v2, d2);
        acc8s(acc, v3, d3);
    }
    for (; p < end; p++) {
        int s0 = __ldg(&g_esrc[p]);
        float d0 = L1 ? __ldg(&g_dis[s0]) : 1.f;
        uint4 v0 = __ldg(&hb[(size_t)s0 * 8 + c]);
        acc8s(acc, v0, d0);
    }
    float out[8];
    #pragma unroll
    for (int j = 0; j < 8; j++) {
        int ff = f + j;
        float sc = __ldg(&g[ff]) * rsqrtf(__ldg(&v[ff]) + 1e-5f);
        out[j] = fmaxf((dis * acc[j] + __ldg(&b[ff]) - __ldg(&m[ff])) * sc + __ldg(&be[ff]), 0.f);
    }
    *reinterpret_cast<float4*>(g_act + (size_t)n * 64 + f)     = make_float4(out[0], out[1], out[2], out[3]);
    *reinterpret_cast<float4*>(g_act + (size_t)n * 64 + f + 4) = make_float4(out[4], out[5], out[6], out[7]);
}

// ---- fused aggregation + relu + mean-pool, 128-wide: 16 threads/node ----
__global__ void k_agg128(const float* __restrict__ b3, const void* __restrict__ batch) {
    int t = blockIdx.x * blockDim.x + threadIdx.x;
    int n = t >> 4;
    if (n >= NN) return;
    int c = t & 15;
    int f = c * 8;
    int deg = g_deg[n];
    int off = g_boff[n >> 10] + g_scan[n] - deg;
    float acc[8];
    {
        float4 a0 = *reinterpret_cast<const float4*>(g_h + (size_t)n * 128 + f);
        float4 a1 = *reinterpret_cast<const float4*>(g_h + (size_t)n * 128 + f + 4);
        acc[0] = a0.x; acc[1] = a0.y; acc[2] = a0.z; acc[3] = a0.w;
        acc[4] = a1.x; acc[5] = a1.y; acc[6] = a1.z; acc[7] = a1.w;
    }
    const uint4* hb = reinterpret_cast<const uint4*>(g_hb);  // 16 uint4 per 128-row
    int p = off, end = off + deg;
    for (; p + 3 < end; p += 4) {
        int s0 = __ldg(&g_esrc[p]);
        int s1 = __ldg(&g_esrc[p + 1]);
        int s2 = __ldg(&g_esrc[p + 2]);
        int s3 = __ldg(&g_esrc[p + 3]);
        uint4 v0 = __ldg(&hb[(size_t)s0 * 16 + c]);
        uint4 v1 = __ldg(&hb[(size_t)s1 * 16 + c]);
        uint4 v2 = __ldg(&hb[(size_t)s2 * 16 + c]);
        uint4 v3 = __ldg(&hb[(size_t)s3 * 16 + c]);
        acc8s(acc, v0, 1.f);
        acc8s(acc, v1, 1.f);
        acc8s(acc, v2, 1.f);
        acc8s(acc, v3, 1.f);
    }
    for (; p < end; p++) {
        int s0 = __ldg(&g_esrc[p]);
        uint4 v0 = __ldg(&hb[(size_t)s0 * 16 + c]);
        acc8s(acc, v0, 1.f);
    }
    float dis = g_dis[n];
    float4 o0, o1;
    o0.x = fmaxf(dis * acc[0] + __ldg(&b3[f + 0]), 0.f);
    o0.y = fmaxf(dis * acc[1] + __ldg(&b3[f + 1]), 0.f);
    o0.z = fmaxf(dis * acc[2] + __ldg(&b3[f + 2]), 0.f);
    o0.w = fmaxf(dis * acc[3] + __ldg(&b3[f + 3]), 0.f);
    o1.x = fmaxf(dis * acc[4] + __ldg(&b3[f + 4]), 0.f);
    o1.y = fmaxf(dis * acc[5] + __ldg(&b3[f + 5]), 0.f);
    o1.z = fmaxf(dis * acc[6] + __ldg(&b3[f + 6]), 0.f);
    o1.w = fmaxf(dis * acc[7] + __ldg(&b3[f + 7]), 0.f);
    int bg = load_idx64(batch, n, g_is64);
    if ((unsigned)bg >= BB) bg = 0;
    red_add_v4(g_sums + bg * 128 + f,     o0);
    red_add_v4(g_sums + bg * 128 + f + 4, o1);
    if (c == 0) atomicAdd(&g_cnt[bg], 1.f);
}

// ---- finalize + cleanup for next call ----
__global__ void k_final(float* __restrict__ out) {
    int i = blockIdx.x * blockDim.x + threadIdx.x;
    if (i < BB * 128) out[i] = g_sums[i] / fmaxf(g_cnt[i >> 7], 1.f);
    if (i < NN) { g_deg[i] = 0; g_cur[i] = 0; }
    if (i == 0) g_tick = 0;
}

extern "C" void kernel_launch(void* const* d_in, const int* in_sizes, int n_in,
                              void* d_out, int out_size) {
    const float* x   = (const float*)d_in[0];
    const void*  ei  = d_in[1];
    const void*  bat = d_in[2];
    const float* W1 = (const float*)d_in[3];
    const float* b1 = (const float*)d_in[4];
    const float* W2 = (const float*)d_in[5];
    const float* b2 = (const float*)d_in[6];
    const float* W3 = (const float*)d_in[7];
    const float* b3 = (const float*)d_in[8];
    const float* g1 = (const float*)d_in[9];
    const float* be1 = (const float*)d_in[10];
    const float* m1 = (const float*)d_in[11];
    const float* v1 = (const float*)d_in[12];
    const float* g2 = (const float*)d_in[13];
    const float* be2 = (const float*)d_in[14];
    const float* m2 = (const float*)d_in[15];
    const float* v2 = (const float*)d_in[16];

    const int TB = 256;

    k_l1<<<GBK + EBK, TB>>>(x, W1, ei);                          // 0: gemm1+hist
    k_scan12<<<NCH, 1024>>>();                                   // 1
    k_sort<<<EBK, TB>>>(ei);                                     // 2
    k_agg64<true><<<(NN * 8 + TB - 1) / TB, TB>>>(b1, g1, be1, m1, v1);   // 3 <- profiled
    k_gemm<64, 64, 32><<<(NN + 31) / 32, TB>>>(W2);              // 4
    k_agg64<false><<<(NN * 8 + TB - 1) / TB, TB>>>(b2, g2, be2, m2, v2);  // 5
    k_gemm<64, 128, 16><<<(NN + 15) / 16, TB>>>(W3);             // 6
    k_agg128<<<(NN * 16 + TB - 1) / TB, TB>>>(b3, bat);          // 7
    k_final<<<(NN + TB - 1) / TB, TB>>>((float*)d_out);          // 8
}

// round 14
// speedup vs baseline: 1.3857x; 1.2319x over previous
#include <cuda_runtime.h>
#include <cuda_bf16.h>

#define NN 100000
#define EE 1600000
#define BB 256
#define NCH 98          // ceil(NN / 1024)
#define EBK 6250        // edge blocks (256 edges each)
#define XBK 1563        // xs blocks (NN*4/256)

// ---- scratch (device globals; zeroed at load; recycled via end-of-call cleanup) ----
__device__ __align__(128) float g_u[(size_t)NN * 64];             // aggregated features (fp32)
__device__ __align__(128) __nv_bfloat16 g_hb[(size_t)NN * 64];    // dis-scaled features (bf16)
__device__ __align__(128) float g_dis[NN];                        // rsqrt(deg+1)
__device__ int   g_deg[NN];     // in-degree   (zeroed by k_final for next call)
__device__ int   g_cur[NN];     // sort cursor (zeroed by k_final)
__device__ int   g_scan[NN];    // chunk-local inclusive scan
__device__ int   g_bsum[NCH];
__device__ int   g_boff[NCH];
__device__ int   g_esrc[EE];
__device__ int   g_tick;        // scan ticket (zeroed by k_final)
__device__ __align__(128) float g_sums[BB * 128];  // zeroed by launch 0
__device__ float g_cnt[BB];                        // zeroed by launch 0
__device__ int   g_is64;

__device__ __forceinline__ void red_add_v4(float* addr, float4 v) {
    unsigned long long ga = (unsigned long long)__cvta_generic_to_global(addr);
    asm volatile("red.global.add.v4.f32 [%0], {%1,%2,%3,%4};"
                 :: "l"(ga), "f"(v.x), "f"(v.y), "f"(v.z), "f"(v.w) : "memory");
}

// per-warp dtype detection: int64 storage of small ints -> odd 32-bit words all zero
__device__ __forceinline__ int detect64(const int* raw) {
    int lane = threadIdx.x & 31;
    int w = (lane < 16) ? raw[2 * lane + 1] : 0;
    return __ballot_sync(0xffffffffu, w != 0) == 0u;
}

__device__ __forceinline__ int load_idx64(const void* p, long long i, int is64) {
    return is64 ? (int)((const long long*)p)[i] : ((const int*)p)[i];
}

// accumulate 8 bf16 (one uint4) into 8 fp32 accumulators
__device__ __forceinline__ void acc8(float* acc, uint4 pk) {
    const __nv_bfloat162* b2 = reinterpret_cast<const __nv_bfloat162*>(&pk);
    #pragma unroll
    for (int j = 0; j < 4; j++) {
        float2 f2 = __bfloat1622float2(b2[j]);
        acc[j * 2 + 0] += f2.x;
        acc[j * 2 + 1] += f2.y;
    }
}

__device__ __forceinline__ uint4 pack8(const float* o) {
    __nv_bfloat162 q0 = __floats2bfloat162_rn(o[0], o[1]);
    __nv_bfloat162 q1 = __floats2bfloat162_rn(o[2], o[3]);
    __nv_bfloat162 q2 = __floats2bfloat162_rn(o[4], o[5]);
    __nv_bfloat162 q3 = __floats2bfloat162_rn(o[6], o[7]);
    uint4 pk;
    pk.x = *reinterpret_cast<unsigned*>(&q0);
    pk.y = *reinterpret_cast<unsigned*>(&q1);
    pk.z = *reinterpret_cast<unsigned*>(&q2);
    pk.w = *reinterpret_cast<unsigned*>(&q3);
    return pk;
}

// ---- launch 0: edge histogram + pool zero + is64 ----
__global__ void k_hist(const void* __restrict__ ei) {
    int e = blockIdx.x * 256 + threadIdx.x;
    int is64 = detect64((const int*)ei);
    if (e < BB * 128) g_sums[e] = 0.f;
    if (e < BB) g_cnt[e] = 0.f;
    if (e == 0) g_is64 = is64;
    if (e >= EE) return;
    int d = load_idx64(ei, (long long)EE + e, is64);
    if ((unsigned)d >= NN) d = 0;
    atomicAdd(&g_deg[d], 1);
}

// ---- launch 1: chunk scans + dis, last block scans chunk totals ----
__global__ void k_scan12() {
    __shared__ int s[1024];
    __shared__ int s2[128];
    __shared__ int slast;
    int t = threadIdx.x;
    int i = blockIdx.x * 1024 + t;
    int v = (i < NN) ? g_deg[i] : 0;
    if (i < NN) g_dis[i] = rsqrtf((float)v + 1.f);
    s[t] = v;
    __syncthreads();
    #pragma unroll
    for (int d = 1; d < 1024; d <<= 1) {
        int add = (t >= d) ? s[t - d] : 0;
        __syncthreads();
        s[t] += add;
        __syncthreads();
    }
    if (i < NN) g_scan[i] = s[t];
    if (t == 1023) g_bsum[blockIdx.x] = s[1023];
    __threadfence();
    __syncthreads();
    if (t == 0) slast = (atomicAdd(&g_tick, 1) == NCH - 1) ? 1 : 0;
    __syncthreads();
    if (slast) {
        __threadfence();
        int v2 = (t < NCH) ? g_bsum[t] : 0;
        if (t < 128) s2[t] = v2;
        __syncthreads();
        #pragma unroll
        for (int d = 1; d < 128; d <<= 1) {
            int add = (t >= d && t < 128) ? s2[t - d] : 0;
            __syncthreads();
            if (t < 128) s2[t] += add;
            __syncthreads();
        }
        if (t < NCH) g_boff[t] = s2[t] - v2;   // exclusive
    }
}

// ---- launch 2: counting-sort edges by dst  +  xs = dis*x (bf16, 22->32 pad) ----
__global__ void k_sortxs(const void* __restrict__ ei, const float* __restrict__ x) {
    int tid = threadIdx.x;
    if (blockIdx.x < EBK) {
        int e = blockIdx.x * 256 + tid;
        int is64 = detect64((const int*)ei);
        if (e >= EE) return;
        int sIdx = load_idx64(ei, e, is64);
        int d = load_idx64(ei, (long long)EE + e, is64);
        if ((unsigned)sIdx >= NN) sIdx = 0;
        if ((unsigned)d >= NN) d = 0;
        int off = g_boff[d >> 10] + g_scan[d] - g_deg[d];
        int p = off + atomicAdd(&g_cur[d], 1);
        g_esrc[p] = sIdx;
    } else {
        int j = (blockIdx.x - EBK) * 256 + tid;
        int n = j >> 2;
        if (n >= NN) return;
        int q = j & 3;
        float dis = g_dis[n];
        float o[8];
        #pragma unroll
        for (int k = 0; k < 8; k++) {
            int col = q * 8 + k;
            o[k] = (col < 22) ? dis * x[(size_t)n * 22 + col] : 0.f;
        }
        reinterpret_cast<uint4*>(g_hb)[(size_t)n * 4 + q] = pack8(o);
    }
}

// ---- aggregation: u[n] = sum_src hb[src] + hb[n]   (COLS/8 threads per node) ----
template <int COLS>
__global__ void k_agg() {
    constexpr int TPN = COLS / 8;
    int t = blockIdx.x * blockDim.x + threadIdx.x;
    int n = t / TPN;
    if (n >= NN) return;
    int c = t % TPN;
    int deg = g_deg[n];
    int off = g_boff[n >> 10] + g_scan[n] - deg;
    const uint4* hb = reinterpret_cast<const uint4*>(g_hb);
    float acc[8];
    {
        uint4 self = __ldg(&hb[(size_t)n * TPN + c]);
        const __nv_bfloat162* b2 = reinterpret_cast<const __nv_bfloat162*>(&self);
        #pragma unroll
        for (int j = 0; j < 4; j++) {
            float2 f2 = __bfloat1622float2(b2[j]);
            acc[j * 2 + 0] = f2.x;
            acc[j * 2 + 1] = f2.y;
        }
    }
    int p = off, end = off + deg;
    for (; p + 3 < end; p += 4) {
        int s0 = __ldg(&g_esrc[p]);
        int s1 = __ldg(&g_esrc[p + 1]);
        int s2 = __ldg(&g_esrc[p + 2]);
        int s3 = __ldg(&g_esrc[p + 3]);
        uint4 v0 = __ldg(&hb[(size_t)s0 * TPN + c]);
        uint4 v1 = __ldg(&hb[(size_t)s1 * TPN + c]);
        uint4 v2 = __ldg(&hb[(size_t)s2 * TPN + c]);
        uint4 v3 = __ldg(&hb[(size_t)s3 * TPN + c]);
        acc8(acc, v0);
        acc8(acc, v1);
        acc8(acc, v2);
        acc8(acc, v3);
    }
    for (; p < end; p++) {
        int s0 = __ldg(&g_esrc[p]);
        uint4 v0 = __ldg(&hb[(size_t)s0 * TPN + c]);
        acc8(acc, v0);
    }
    size_t ob = (size_t)n * COLS + c * 8;
    *reinterpret_cast<float4*>(g_u + ob)     = make_float4(acc[0], acc[1], acc[2], acc[3]);
    *reinterpret_cast<float4*>(g_u + ob + 4) = make_float4(acc[4], acc[5], acc[6], acc[7]);
}

// ---- GEMM + BN/ReLU epilogue: hb = dis * relu(bn(dis*(u@W) + b)) as bf16 ----
// FIN=32 pads W (22 real rows); FIN=64 vector-loads W.
template <int FIN, int FOUT, int NPB, int WROWS>
__global__ void k_gemm_epi(const float* __restrict__ W, const float* __restrict__ b,
                           const float* __restrict__ g, const float* __restrict__ be,
                           const float* __restrict__ m, const float* __restrict__ v) {
    constexpr int FG = FOUT / 4, RS = 256 / FG, RPT = NPB / RS;
    __shared__ float sW[FIN * FOUT];
    __shared__ float sX[NPB * FIN];
    const int tid = threadIdx.x;
    for (int i = tid; i < FIN * FOUT; i += 256) {
        int k = i / FOUT;
        sW[i] = (k < WROWS) ? W[(size_t)k * FOUT + (i % FOUT)] : 0.f;
    }
    const int n0 = blockIdx.x * NPB;
    for (int i = tid; i < NPB * FIN / 4; i += 256) {
        int nn = i / (FIN / 4), k4 = i % (FIN / 4);
        int n = n0 + nn;
        reinterpret_cast<float4*>(sX)[i] = (n < NN)
            ? *reinterpret_cast<const float4*>(g_u + (size_t)n * FIN + k4 * 4)
            : make_float4(0.f, 0.f, 0.f, 0.f);
    }
    __syncthreads();
    const int fg = tid % FG, rs = tid / FG;
    float4 acc[RPT];
    #pragma unroll
    for (int r = 0; r < RPT; r++) acc[r] = make_float4(0.f, 0.f, 0.f, 0.f);
    #pragma unroll
    for (int k = 0; k < FIN; k++) {
        float4 w = *reinterpret_cast<const float4*>(&sW[k * FOUT + fg * 4]);
        #pragma unroll
        for (int r = 0; r < RPT; r++) {
            float xv = sX[(rs + r * RS) * FIN + k];
            acc[r].x = fmaf(xv, w.x, acc[r].x);
            acc[r].y = fmaf(xv, w.y, acc[r].y);
            acc[r].z = fmaf(xv, w.z, acc[r].z);
            acc[r].w = fmaf(xv, w.w, acc[r].w);
        }
    }
    int f = fg * 4;
    float4 bb  = *reinterpret_cast<const float4*>(b + f);
    float4 gg  = *reinterpret_cast<const float4*>(g + f);
    float4 bee = *reinterpret_cast<const float4*>(be + f);
    float4 mm  = *reinterpret_cast<const float4*>(m + f);
    float4 vv  = *reinterpret_cast<const float4*>(v + f);
    float4 sc;
    sc.x = gg.x * rsqrtf(vv.x + 1e-5f);
    sc.y = gg.y * rsqrtf(vv.y + 1e-5f);
    sc.z = gg.z * rsqrtf(vv.z + 1e-5f);
    sc.w = gg.w * rsqrtf(vv.w + 1e-5f);
    #pragma unroll
    for (int r = 0; r < RPT; r++) {
        int n = n0 + rs + r * RS;
        if (n >= NN) continue;
        float dis = g_dis[n];
        float a0 = fmaxf((dis * acc[r].x + bb.x - mm.x) * sc.x + bee.x, 0.f) * dis;
        float a1 = fmaxf((dis * acc[r].y + bb.y - mm.y) * sc.y + bee.y, 0.f) * dis;
        float a2 = fmaxf((dis * acc[r].z + bb.z - mm.z) * sc.z + bee.z, 0.f) * dis;
        float a3 = fmaxf((dis * acc[r].w + bb.w - mm.w) * sc.w + bee.w, 0.f) * dis;
        __nv_bfloat162 q0 = __floats2bfloat162_rn(a0, a1);
        __nv_bfloat162 q1 = __floats2bfloat162_rn(a2, a3);
        uint2 pk;
        pk.x = *reinterpret_cast<unsigned*>(&q0);
        pk.y = *reinterpret_cast<unsigned*>(&q1);
        *reinterpret_cast<uint2*>(g_hb + (size_t)n * FOUT + f) = pk;
    }
}

// ---- layer-3 GEMM + ReLU + mean-pool epilogue (64 -> 128) ----
__global__ void k_gemm_pool(const float* __restrict__ W, const float* __restrict__ b3,
                            const void* __restrict__ batch) {
    constexpr int FIN = 64, FOUT = 128, NPB = 16;
    constexpr int FG = FOUT / 4, RS = 256 / FG, RPT = NPB / RS;   // 32, 8, 2
    __shared__ float sW[FIN * FOUT];
    __shared__ float sX[NPB * FIN];
    const int tid = threadIdx.x;
    for (int i = tid; i < FIN * FOUT / 4; i += 256)
        reinterpret_cast<float4*>(sW)[i] = reinterpret_cast<const float4*>(W)[i];
    const int n0 = blockIdx.x * NPB;
    for (int i = tid; i < NPB * FIN / 4; i += 256) {
        int nn = i / (FIN / 4), k4 = i % (FIN / 4);
        int n = n0 + nn;
        reinterpret_cast<float4*>(sX)[i] = (n < NN)
            ? *reinterpret_cast<const float4*>(g_u + (size_t)n * FIN + k4 * 4)
            : make_float4(0.f, 0.f, 0.f, 0.f);
    }
    __syncthreads();
    const int fg = tid % FG, rs = tid / FG;
    float4 acc[RPT];
    #pragma unroll
    for (int r = 0; r < RPT; r++) acc[r] = make_float4(0.f, 0.f, 0.f, 0.f);
    #pragma unroll
    for (int k = 0; k < FIN; k++) {
        float4 w = *reinterpret_cast<const float4*>(&sW[k * FOUT + fg * 4]);
        #pragma unroll
        for (int r = 0; r < RPT; r++) {
            float xv = sX[(rs + r * RS) * FIN + k];
            acc[r].x = fmaf(xv, w.x, acc[r].x);
            acc[r].y = fmaf(xv, w.y, acc[r].y);
            acc[r].z = fmaf(xv, w.z, acc[r].z);
            acc[r].w = fmaf(xv, w.w, acc[r].w);
        }
    }
    int f = fg * 4;
    float4 bb = *reinterpret_cast<const float4*>(b3 + f);
    int is64 = g_is64;
    #pragma unroll
    for (int r = 0; r < RPT; r++) {
        int n = n0 + rs + r * RS;
        if (n >= NN) continue;
        float dis = g_dis[n];
        float4 o;
        o.x = fmaxf(dis * acc[r].x + bb.x, 0.f);
        o.y = fmaxf(dis * acc[r].y + bb.y, 0.f);
        o.z = fmaxf(dis * acc[r].z + bb.z, 0.f);
        o.w = fmaxf(dis * acc[r].w + bb.w, 0.f);
        int bg = load_idx64(batch, n, is64);
        if ((unsigned)bg >= BB) bg = 0;
        red_add_v4(g_sums + bg * 128 + f, o);
        if (fg == 0) atomicAdd(&g_cnt[bg], 1.f);
    }
}

// ---- finalize + cleanup for next call ----
__global__ void k_final(float* __restrict__ out) {
    int i = blockIdx.x * blockDim.x + threadIdx.x;
    if (i < BB * 128) out[i] = g_sums[i] / fmaxf(g_cnt[i >> 7], 1.f);
    if (i < NN) { g_deg[i] = 0; g_cur[i] = 0; }
    if (i == 0) g_tick = 0;
}

extern "C" void kernel_launch(void* const* d_in, const int* in_sizes, int n_in,
                              void* d_out, int out_size) {
    const float* x   = (const float*)d_in[0];
    const void*  ei  = d_in[1];
    const void*  bat = d_in[2];
    const float* W1 = (const float*)d_in[3];
    const float* b1 = (const float*)d_in[4];
    const float* W2 = (const float*)d_in[5];
    const float* b2 = (const float*)d_in[6];
    const float* W3 = (const float*)d_in[7];
    const float* b3 = (const float*)d_in[8];
    const float* g1 = (const float*)d_in[9];
    const float* be1 = (const float*)d_in[10];
    const float* m1 = (const float*)d_in[11];
    const float* v1 = (const float*)d_in[12];
    const float* g2 = (const float*)d_in[13];
    const float* be2 = (const float*)d_in[14];
    const float* m2 = (const float*)d_in[15];
    const float* v2 = (const float*)d_in[16];

    const int TB = 256;

    k_hist<<<EBK, TB>>>(ei);                                     // 0
    k_scan12<<<NCH, 1024>>>();                                   // 1
    k_sortxs<<<EBK + XBK, TB>>>(ei, x);                          // 2
    k_agg<32><<<(NN * 4 + TB - 1) / TB, TB>>>();                 // 3 <- profiled
    k_gemm_epi<32, 64, 32, 22><<<(NN + 31) / 32, TB>>>(W1, b1, g1, be1, m1, v1);  // 4
    k_agg<64><<<(NN * 8 + TB - 1) / TB, TB>>>();                 // 5
    k_gemm_epi<64, 64, 32, 64><<<(NN + 31) / 32, TB>>>(W2, b2, g2, be2, m2, v2);  // 6
    k_agg<64><<<(NN * 8 + TB - 1) / TB, TB>>>();                 // 7
    k_gemm_pool<<<(NN + 15) / 16, TB>>>(W3, b3, bat);            // 8
    k_final<<<(NN + TB - 1) / TB, TB>>>((float*)d_out);          // 9
}